// round 10
// baseline (speedup 1.0000x reference)
#include <cuda_runtime.h>
#include <mma.h>
using namespace nvcuda;

// ---------------- problem constants ----------------
#define B_    4
#define C_    64
#define NA_   25
#define D_    128
#define H_    32
#define W_    32
#define S_    25600      // NA*H*W
#define NPOS_ 102400     // B*S
#define M_SF  1024
#define K_SF  800
#define M_AF  160
#define K_AF  5120
#define M_SA  160
#define K_SA  10240
#define MP_   192                  // padded row count for af/sa (wmma-friendly)
#define PART_SZ (MP_*MP_)          // 36864
#define FOFF2 (64*PART_SZ)         // finals offset in g_att (16ch*4b partials max)

// ---------------- scratch (device globals; no allocation) ----------------
__device__ float g_q [B_*D_*S_];
__device__ float g_kv[B_*D_*S_];

__device__ float g_sfQ[B_*M_SF*K_SF];
__device__ float g_sfK[B_*M_SF*K_SF];
__device__ float g_sfO[B_*M_SF*K_SF];
__device__ float g_afQ[B_*MP_*K_AF];   // pad rows 160..191 stay zero (never written)
__device__ float g_afK[B_*MP_*K_AF];
__device__ float g_afO[B_*MP_*K_AF];
__device__ float g_saQ[B_*MP_*K_SA];
__device__ float g_saK[B_*MP_*K_SA];
__device__ float g_saO[B_*MP_*K_SA];

__device__ float g_ivq_sf[B_*M_SF];
__device__ float g_ivk_sf[B_*M_SF];
__device__ float g_ivq_af[B_*M_AF];
__device__ float g_ivk_af[B_*M_AF];
__device__ float g_ivq_sa[B_*M_SA];
__device__ float g_ivk_sa[B_*M_SA];

__device__ float g_att[B_*M_SF*M_SF];   // sf scores / af-sa partials+finals

__device__ float g_ct[NPOS_*D_];
__device__ float g_ln[NPOS_*D_];
__device__ float g_h1[NPOS_*D_];

// pre-rounded weights
__device__ float g_wrk[57344];

__device__ __forceinline__ float tf32r(float x) {
    float y;
    asm("cvt.rna.tf32.f32 %0, %1;" : "=f"(y) : "f"(x));
    return y;
}

using FragAr = wmma::fragment<wmma::matrix_a, 16,16,8, wmma::precision::tf32, wmma::row_major>;
using FragAc = wmma::fragment<wmma::matrix_a, 16,16,8, wmma::precision::tf32, wmma::col_major>;
using FragBr = wmma::fragment<wmma::matrix_b, 16,16,8, wmma::precision::tf32, wmma::row_major>;
using FragBc = wmma::fragment<wmma::matrix_b, 16,16,8, wmma::precision::tf32, wmma::col_major>;
using FragC  = wmma::fragment<wmma::accumulator, 16,16,8, float>;

template<class F> __device__ __forceinline__ void cvt_tf32(F& f) {
    #pragma unroll
    for (int i = 0; i < f.num_elements; i++) f.x[i] = wmma::__float_to_tf32(f.x[i]);
}

// ---------------- 0) pre-round all weights into g_wrk ----------------
__global__ void k_roundw(const float* __restrict__ Win, const float* __restrict__ Wkv,
                         const float* __restrict__ Wm1, const float* __restrict__ Wm2,
                         const float* __restrict__ Wot) {
    int i = blockIdx.x*256 + threadIdx.x;
    if (i >= 57344) return;
    const float* src;
    int off;
    if (i < 8192)       { src = Win; off = 0; }
    else if (i < 16384) { src = Wkv; off = 8192; }
    else if (i < 32768) { src = Wm1; off = 16384; }
    else if (i < 49152) { src = Wm2; off = 32768; }
    else                { src = Wot; off = 49152; }
    g_wrk[i] = tf32r(src[i - off]);
}

// ===================================================================
// 1) token projection
// ===================================================================
template<int WHICH>
__global__ __launch_bounds__(256) void k_tokens_wmma(const float* __restrict__ x) {
    const float* Wm = g_wrk + (WHICH == 0 ? 0 : 8192);
    float* y = (WHICH == 0) ? g_q : g_kv;
    int m0 = blockIdx.x * 128;
    int b = m0 / S_, s0 = m0 % S_;
    const float* xb = x + (size_t)b*C_*S_ + s0;
    int wid = threadIdx.x >> 5, wm = wid & 1, wn = wid >> 1;
    FragC acc[4][2];
    #pragma unroll
    for (int f = 0; f < 4; f++)
        #pragma unroll
        for (int j = 0; j < 2; j++) wmma::fill_fragment(acc[f][j], 0.f);
    for (int k = 0; k < C_; k += 8) {
        FragBr bf[2];
        #pragma unroll
        for (int j = 0; j < 2; j++)
            wmma::load_matrix_sync(bf[j], Wm + (size_t)k*D_ + wn*32 + j*16, D_);
        #pragma unroll
        for (int f = 0; f < 4; f++) {
            FragAc af;
            wmma::load_matrix_sync(af, xb + (size_t)k*S_ + wm*64 + f*16, S_);
            cvt_tf32(af);
            #pragma unroll
            for (int j = 0; j < 2; j++) wmma::mma_sync(acc[f][j], af, bf[j], acc[f][j]);
        }
    }
    float* yb = y + (size_t)b*D_*S_ + s0;
    #pragma unroll
    for (int f = 0; f < 4; f++)
        #pragma unroll
        for (int j = 0; j < 2; j++)
            wmma::store_matrix_sync(yb + (size_t)(wn*32 + j*16)*S_ + wm*64 + f*16,
                                    acc[f][j], S_, wmma::mem_col_major);
}

// ---------------- 2) fold gather + inverse L2 norms (tf32-rounded output) ----------------
template<int TYPE>
__global__ void k_fold() {
    constexpr int MM  = TYPE==0 ? M_SF : (TYPE==1 ? M_AF : M_SA);
    constexpr int KK  = TYPE==0 ? K_SF : (TYPE==1 ? K_AF : K_SA);
    constexpr int OFF = TYPE==0 ? 0 : (TYPE==1 ? 32 : 64);
    constexpr int RS  = TYPE==0 ? M_SF : MP_;   // dst row stride count per batch
    int row = blockIdx.x;
    int isK = blockIdx.y;
    int b = row / MM, m = row % MM;
    const float* src = isK ? g_kv : g_q;
    float* dst; float* ivd;
    if (TYPE==0) { dst = isK ? g_sfK : g_sfQ; ivd = isK ? g_ivk_sf : g_ivq_sf; }
    else if (TYPE==1) { dst = isK ? g_afK : g_afQ; ivd = isK ? g_ivk_af : g_ivq_af; }
    else { dst = isK ? g_saK : g_saQ; ivd = isK ? g_ivk_sa : g_ivq_sa; }
    const float* base = src + ((size_t)b*D_ + OFF)*S_;
    float* drow = dst + ((size_t)b*RS + m)*KK;
    int t = threadIdx.x;
    float ss = 0.f;
    if (TYPE == 0) {
        int ch = m >> 5, hh = m & 31;
        const float* bp = base + (size_t)ch*S_ + hh*W_;
        for (int kk = t; kk < KK; kk += 256) {
            int n = kk >> 5, ww = kk & 31;
            float v = tf32r(bp[n*(H_*W_) + ww]);
            drow[kk] = v;
            ss += v*v;
        }
    } else if (TYPE == 1) {
        int ch = m / 5, uu = m % 5;
        const float* bp = base + (size_t)ch*S_;
        for (int k = t; k < KK; k += 256) {
            int hh = k / 160, vv = (k >> 5) % 5, ww = k & 31;
            int n = uu*5 + vv;
            float v = tf32r(bp[n*(H_*W_) + hh*W_ + ww]);
            drow[k] = v;
            ss += v*v;
        }
    } else {
        int hh = m / 5, uu = m % 5;
        for (int k = t; k < KK; k += 256) {
            int ch = k / 160, vv = (k >> 5) % 5, ww = k & 31;
            int n = uu*5 + vv;
            float v = tf32r(base[(size_t)ch*S_ + n*(H_*W_) + hh*W_ + ww]);
            drow[k] = v;
            ss += v*v;
        }
    }
    __shared__ float red[256];
    red[t] = ss; __syncthreads();
    for (int st = 128; st > 0; st >>= 1) { if (t < st) red[t] += red[t + st]; __syncthreads(); }
    if (t == 0) ivd[row] = 1.f / fmaxf(sqrtf(red[0]), 1e-12f);
}

// ===================================================================
// 3a) SF raw scores (NT), wmma tf32
// ===================================================================
__global__ __launch_bounds__(256) void k_score_sf() {
    int b = blockIdx.z, m0 = blockIdx.y*128, n0 = blockIdx.x*64;
    if (n0 > m0 + 127) return;
    const float* Ab = g_sfQ + (size_t)b*M_SF*K_SF;
    const float* Bb = g_sfK + (size_t)b*M_SF*K_SF;
    __shared__ __align__(16) float As[2][128][20];
    __shared__ __align__(16) float Bs[2][64][20];
    int t = threadIdx.x;
    int wid = t >> 5, wm = wid & 1, wn = wid >> 1;
    int ar_ = t >> 1, ac_ = (t & 1) * 8;
    int br_ = t >> 2, bc_ = (t & 3) * 4;
    FragC acc[4];
    #pragma unroll
    for (int i = 0; i < 4; i++) wmma::fill_fragment(acc[i], 0.f);
    float4 a0 = *(const float4*)(Ab + (size_t)(m0+ar_)*K_SF + ac_);
    float4 a1 = *(const float4*)(Ab + (size_t)(m0+ar_)*K_SF + ac_ + 4);
    float4 b0 = *(const float4*)(Bb + (size_t)(n0+br_)*K_SF + bc_);
    *(float4*)&As[0][ar_][ac_]   = a0;
    *(float4*)&As[0][ar_][ac_+4] = a1;
    *(float4*)&Bs[0][br_][bc_]   = b0;
    __syncthreads();
    const int nit = K_SF/16;
    for (int it = 0; it < nit; it++) {
        int cur = it & 1;
        if (it + 1 < nit) {
            int k0 = (it+1)*16;
            a0 = *(const float4*)(Ab + (size_t)(m0+ar_)*K_SF + k0 + ac_);
            a1 = *(const float4*)(Ab + (size_t)(m0+ar_)*K_SF + k0 + ac_ + 4);
            b0 = *(const float4*)(Bb + (size_t)(n0+br_)*K_SF + k0 + bc_);
        }
        #pragma unroll
        for (int ks = 0; ks < 16; ks += 8) {
            FragBc bf;
            wmma::load_matrix_sync(bf, &Bs[cur][wn*16][ks], 20);
            #pragma unroll
            for (int f = 0; f < 4; f++) {
                FragAr af;
                wmma::load_matrix_sync(af, &As[cur][wm*64 + f*16][ks], 20);
                wmma::mma_sync(acc[f], af, bf, acc[f]);
            }
        }
        if (it + 1 < nit) {
            int nx = cur ^ 1;
            *(float4*)&As[nx][ar_][ac_]   = a0;
            *(float4*)&As[nx][ar_][ac_+4] = a1;
            *(float4*)&Bs[nx][br_][bc_]   = b0;
            __syncthreads();
        }
    }
    float* att = g_att + (size_t)b*M_SF*M_SF;
    #pragma unroll
    for (int f = 0; f < 4; f++)
        wmma::store_matrix_sync(att + (size_t)(m0 + wm*64 + f*16)*M_SF + n0 + wn*16,
                                acc[f], M_SF, wmma::mem_row_major);
}

// ===================================================================
// 4a) SF softmax
// ===================================================================
__global__ __launch_bounds__(256) void k_softmax_sf() {
    int blk = blockIdx.x;
    int b = blk >> 10, m = blk & 1023;
    float* p = g_att + ((size_t)b*M_SF + m)*M_SF;
    int LIMW = ((m >> 7) + 1) << 7;
    float qn = g_ivq_sf[b*M_SF + m];
    const float* ivk = g_ivk_sf + b*M_SF;
    int t = threadIdx.x;
    __shared__ float red[256];
    float vv[4];
    float mx = -3.4e38f;
    #pragma unroll
    for (int i = 0; i < 4; i++) {
        int k = t + i*256;
        if (k < LIMW) {
            float v = (k <= m) ? p[k]*qn*ivk[k] : -3.4e38f;
            vv[i] = v; mx = fmaxf(mx, v);
        }
    }
    red[t] = mx; __syncthreads();
    for (int st = 128; st > 0; st >>= 1) { if (t < st) red[t] = fmaxf(red[t], red[t+st]); __syncthreads(); }
    mx = red[0]; __syncthreads();
    float s = 0.f;
    #pragma unroll
    for (int i = 0; i < 4; i++) {
        int k = t + i*256;
        if (k < LIMW) {
            float e = (k <= m) ? expf(vv[i] - mx) : 0.f;
            vv[i] = e; s += e;
        }
    }
    red[t] = s; __syncthreads();
    for (int st = 128; st > 0; st >>= 1) { if (t < st) red[t] += red[t+st]; __syncthreads(); }
    float inv = 1.f / red[0];
    #pragma unroll
    for (int i = 0; i < 4; i++) {
        int k = t + i*256;
        if (k < LIMW) p[k] = tf32r(vv[i]*inv);
    }
}

// ===================================================================
// 5a) SF O = P @ V (NN), wmma tf32, causal bound
// ===================================================================
__global__ __launch_bounds__(256) void k_pv_sf() {
    int b = blockIdx.z, m0 = blockIdx.y*128, k0 = blockIdx.x*64;
    const float* Pb = g_att + (size_t)b*M_SF*M_SF;
    const float* Vb = g_sfK + (size_t)b*M_SF*K_SF;
    __shared__ __align__(16) float As[2][128][20];
    __shared__ __align__(16) float Bs[2][16][68];
    int t = threadIdx.x;
    int wid = t >> 5, wm = wid & 1, wn = wid >> 1;
    int ar_ = t >> 1, ac_ = (t & 1) * 8;
    int vr_ = t >> 4, vc_ = (t & 15) * 4;
    bool bok = (k0 + vc_) < K_SF;
    FragC acc[4];
    #pragma unroll
    for (int i = 0; i < 4; i++) wmma::fill_fragment(acc[i], 0.f);
    float4 a0 = *(const float4*)(Pb + (size_t)(m0+ar_)*M_SF + ac_);
    float4 a1 = *(const float4*)(Pb + (size_t)(m0+ar_)*M_SF + ac_ + 4);
    float4 b0 = bok ? *(const float4*)(Vb + (size_t)vr_*K_SF + k0 + vc_) : make_float4(0,0,0,0);
    *(float4*)&As[0][ar_][ac_]   = a0;
    *(float4*)&As[0][ar_][ac_+4] = a1;
    *(float4*)&Bs[0][vr_][vc_]   = b0;
    __syncthreads();
    const int nit = (m0 + 128) / 16;
    for (int it = 0; it < nit; it++) {
        int cur = it & 1;
        if (it + 1 < nit) {
            int n0 = (it+1)*16;
            a0 = *(const float4*)(Pb + (size_t)(m0+ar_)*M_SF + n0 + ac_);
            a1 = *(const float4*)(Pb + (size_t)(m0+ar_)*M_SF + n0 + ac_ + 4);
            b0 = bok ? *(const float4*)(Vb + (size_t)(n0+vr_)*K_SF + k0 + vc_) : make_float4(0,0,0,0);
        }
        #pragma unroll
        for (int ks = 0; ks < 16; ks += 8) {
            FragBr bf;
            wmma::load_matrix_sync(bf, &Bs[cur][ks][wn*16], 68);
            #pragma unroll
            for (int f = 0; f < 4; f++) {
                FragAr af;
                wmma::load_matrix_sync(af, &As[cur][wm*64 + f*16][ks], 20);
                wmma::mma_sync(acc[f], af, bf, acc[f]);
            }
        }
        if (it + 1 < nit) {
            int nx = cur ^ 1;
            *(float4*)&As[nx][ar_][ac_]   = a0;
            *(float4*)&As[nx][ar_][ac_+4] = a1;
            *(float4*)&Bs[nx][vr_][vc_]   = b0;
            __syncthreads();
        }
    }
    float* O = g_sfO + (size_t)b*M_SF*K_SF;
    int col0 = k0 + wn*16;
    if (col0 < K_SF) {
        #pragma unroll
        for (int f = 0; f < 4; f++)
            wmma::store_matrix_sync(O + (size_t)(m0 + wm*64 + f*16)*K_SF + col0,
                                    acc[f], K_SF, wmma::mem_row_major);
    }
}

// ===================================================================
// 3b) af/sa raw scores, split-K, wmma tf32 (64x64 tile, 8 warps)
//     partials at stride MP_=192 (pad rows of Q/K are zero)
// ===================================================================
template<int TYPE>
__global__ __launch_bounds__(256) void k_score_small_wmma() {
    constexpr int KK = TYPE==1 ? K_AF : K_SA;
    constexpr int CH = TYPE==1 ? 8 : 16;
    constexpr int CHK = KK / CH;             // 640
    const float* Qf = TYPE==1 ? g_afQ : g_saQ;
    const float* Kf = TYPE==1 ? g_afK : g_saK;
    int z = blockIdx.z;
    int b = z / CH, ch = z % CH;
    int m0 = blockIdx.y*64, n0 = blockIdx.x*64;
    if (n0 > m0 + 63) return;
    const float* Ab = Qf + (size_t)b*MP_*KK;
    const float* Bb = Kf + (size_t)b*MP_*KK;
    __shared__ __align__(16) float As[2][64][20];
    __shared__ __align__(16) float Bs[2][64][20];
    int t = threadIdx.x;
    int wid = t >> 5, wm = wid & 3, wn = wid >> 2;
    int lr = t >> 2, lc = (t & 3) * 4;
    FragC acc[2];
    #pragma unroll
    for (int j = 0; j < 2; j++) wmma::fill_fragment(acc[j], 0.f);
    int kbeg = ch*CHK;
    float4 a0 = *(const float4*)(Ab + (size_t)(m0+lr)*KK + kbeg + lc);
    float4 b0 = *(const float4*)(Bb + (size_t)(n0+lr)*KK + kbeg + lc);
    *(float4*)&As[0][lr][lc] = a0;
    *(float4*)&Bs[0][lr][lc] = b0;
    __syncthreads();
    const int nit = CHK/16;                  // 40
    for (int it = 0; it < nit; it++) {
        int cur = it & 1;
        if (it + 1 < nit) {
            int k0 = kbeg + (it+1)*16;
            a0 = *(const float4*)(Ab + (size_t)(m0+lr)*KK + k0 + lc);
            b0 = *(const float4*)(Bb + (size_t)(n0+lr)*KK + k0 + lc);
        }
        #pragma unroll
        for (int ks = 0; ks < 16; ks += 8) {
            FragAr af;
            wmma::load_matrix_sync(af, &As[cur][wm*16][ks], 20);
            #pragma unroll
            for (int j = 0; j < 2; j++) {
                FragBc bf;
                wmma::load_matrix_sync(bf, &Bs[cur][wn*32 + j*16][ks], 20);
                wmma::mma_sync(acc[j], af, bf, acc[j]);
            }
        }
        if (it + 1 < nit) {
            int nx = cur ^ 1;
            *(float4*)&As[nx][lr][lc] = a0;
            *(float4*)&Bs[nx][lr][lc] = b0;
            __syncthreads();
        }
    }
    float* part = g_att + (size_t)(ch*B_ + b)*PART_SZ;
    #pragma unroll
    for (int j = 0; j < 2; j++)
        wmma::store_matrix_sync(part + (size_t)(m0 + wm*16)*MP_ + n0 + wn*32 + j*16,
                                acc[j], MP_, wmma::mem_row_major);
}

// ---------------- 4b) af/sa softmax over split-K partials (padded strides) ----------------
template<int TYPE>
__global__ __launch_bounds__(256) void k_softmax_small() {
    constexpr int MM = 160;
    constexpr int CH = TYPE==1 ? 8 : 16;
    const float* ivq = TYPE==1 ? g_ivq_af : g_ivq_sa;
    const float* ivk = TYPE==1 ? g_ivk_af : g_ivk_sa;
    int blk = blockIdx.x;
    int b = blk / MM, m = blk % MM;
    int t = threadIdx.x;
    float v = -3.4e38f;
    if (t < MM && t <= m) {
        float s = 0.f;
        #pragma unroll 4
        for (int ch = 0; ch < CH; ch++)
            s += g_att[(size_t)(ch*B_ + b)*PART_SZ + (size_t)m*MP_ + t];
        v = s * ivq[b*MM + m] * ivk[b*MM + t];
    }
    __shared__ float red[256];
    red[t] = v; __syncthreads();
    for (int st = 128; st > 0; st >>= 1) { if (t < st) red[t] = fmaxf(red[t], red[t+st]); __syncthreads(); }
    float mx = red[0]; __syncthreads();
    float e = (t < MM && t <= m) ? expf(v - mx) : 0.f;
    red[t] = e; __syncthreads();
    for (int st = 128; st > 0; st >>= 1) { if (t < st) red[t] += red[t+st]; __syncthreads(); }
    float inv = 1.f / red[0];
    if (t < MP_) g_att[FOFF2 + (size_t)b*PART_SZ + (size_t)m*MP_ + t] =
        (t < MM && t <= m) ? tf32r(e*inv) : 0.f;
}

// ===================================================================
// 5b) af/sa O = P @ V, wmma tf32 (64x64 tile, causal bound, padded rows)
// ===================================================================
template<int TYPE>
__global__ __launch_bounds__(256) void k_pv_small_wmma() {
    constexpr int KK = TYPE==1 ? K_AF : K_SA;
    const float* Vb0 = TYPE==1 ? g_afK : g_saK;
    float* O0 = TYPE==1 ? g_afO : g_saO;
    int b = blockIdx.z, m0 = blockIdx.y*64, k0 = blockIdx.x*64;
    const float* Pb = g_att + FOFF2 + (size_t)b*PART_SZ;
    const float* Vb = Vb0 + (size_t)b*MP_*KK;
    float* O = O0 + (size_t)b*MP_*KK;
    __shared__ __align__(16) float As[2][64][20];
    __shared__ __align__(16) float Bs[2][16][68];
    int t = threadIdx.x;
    int wid = t >> 5, wm = wid & 3, wn = wid >> 2;
    int lr = t >> 2, lc = (t & 3) * 4;       // P loader
    int vr = t >> 4, vc = (t & 15) * 4;      // V loader
    FragC acc[2];
    #pragma unroll
    for (int j = 0; j < 2; j++) wmma::fill_fragment(acc[j], 0.f);
    float4 a0 = *(const float4*)(Pb + (size_t)(m0+lr)*MP_ + lc);
    float4 b0 = *(const float4*)(Vb + (size_t)vr*KK + k0 + vc);
    *(float4*)&As[0][lr][lc] = a0;
    *(float4*)&Bs[0][vr][vc] = b0;
    __syncthreads();
    const int nit = (m0 + 64) / 16;
    for (int it = 0; it < nit; it++) {
        int cur = it & 1;
        if (it + 1 < nit) {
            int n0 = (it+1)*16;
            a0 = *(const float4*)(Pb + (size_t)(m0+lr)*MP_ + n0 + lc);
            b0 = *(const float4*)(Vb + (size_t)(n0+vr)*KK + k0 + vc);
        }
        #pragma unroll
        for (int ks = 0; ks < 16; ks += 8) {
            FragAr af;
            wmma::load_matrix_sync(af, &As[cur][wm*16][ks], 20);
            #pragma unroll
            for (int j = 0; j < 2; j++) {
                FragBr bf;
                wmma::load_matrix_sync(bf, &Bs[cur][ks][wn*32 + j*16], 68);
                wmma::mma_sync(acc[j], af, bf, acc[j]);
            }
        }
        if (it + 1 < nit) {
            int nx = cur ^ 1;
            *(float4*)&As[nx][lr][lc] = a0;
            *(float4*)&Bs[nx][vr][vc] = b0;
            __syncthreads();
        }
    }
    #pragma unroll
    for (int j = 0; j < 2; j++)
        wmma::store_matrix_sync(O + (size_t)(m0 + wm*16)*KK + k0 + wn*32 + j*16,
                                acc[j], KK, wmma::mem_row_major);
}

// ===================================================================
// 6+7) fused unfold+residual+LayerNorm (padded af/sa strides)
// ===================================================================
__global__ __launch_bounds__(256) void k_combine_ln(const float* __restrict__ gamma,
                                                    const float* __restrict__ beta) {
    int t = threadIdx.x;
    int tok = t >> 7;
    int dc = t & 127;
    int T = blockIdx.x*2 + tok;
    int ww = T & 31, hh = (T >> 5) & 31;
    int bn = T >> 10;
    int b = bn / 25, n = bn % 25;
    int uu = n / 5, vv = n % 5;
    float r = g_kv[((size_t)b*D_ + dc)*S_ + n*(H_*W_) + hh*W_ + ww];
    float o;
    if (dc < 32) {
        int m = dc*32 + hh, k = n*32 + ww;
        o = g_sfO[((size_t)b*M_SF + m)*K_SF + k];
    } else if (dc < 64) {
        int m = (dc-32)*5 + uu, k = (hh*5 + vv)*32 + ww;
        o = g_afO[((size_t)b*MP_ + m)*K_AF + k];
    } else {
        int m = hh*5 + uu, k = ((dc-64)*5 + vv)*32 + ww;
        o = g_saO[((size_t)b*MP_ + m)*K_SA + k];
    }
    float v = o + r;
    g_ct[(size_t)T*D_ + dc] = v;
    float s = v;
    #pragma unroll
    for (int of = 16; of > 0; of >>= 1) s += __shfl_xor_sync(0xffffffffu, s, of);
    __shared__ float wsum[2][4];
    int wg = (t >> 5) & 3;
    if ((t & 31) == 0) wsum[tok][wg] = s;
    __syncthreads();
    float mu = (wsum[tok][0]+wsum[tok][1]+wsum[tok][2]+wsum[tok][3]) * (1.f/128.f);
    float cx = v - mu;
    float sq = cx*cx;
    #pragma unroll
    for (int of = 16; of > 0; of >>= 1) sq += __shfl_xor_sync(0xffffffffu, sq, of);
    __shared__ float wsq[2][4];
    if ((t & 31) == 0) wsq[tok][wg] = sq;
    __syncthreads();
    float var = (wsq[tok][0]+wsq[tok][1]+wsq[tok][2]+wsq[tok][3]) * (1.f/128.f);
    float inv = rsqrtf(var + 1e-5f);
    g_ln[(size_t)T*D_ + dc] = tf32r(cx*inv*gamma[dc] + beta[dc]);
}

// ===================================================================
// 8) MLP gemms, wmma tf32
// ===================================================================
template<int MODE>
__global__ __launch_bounds__(256) void k_mlp_wmma(float* __restrict__ outp) {
    constexpr int NOUT = (MODE == 2) ? 64 : 128;
    constexpr int NF   = (MODE == 2) ? 1 : 2;
    const float* Wm = g_wrk + (MODE == 0 ? 16384 : (MODE == 1 ? 32768 : 49152));
    const float* A = (MODE == 1) ? g_h1 : g_ln;
    int m0 = blockIdx.x * 128;
    __shared__ __align__(16) float As[2][128][20];
    int t = threadIdx.x;
    int wid = t >> 5, wm = wid & 1, wn = wid >> 1;
    int ar_ = t >> 1, ac_ = (t & 1) * 8;
    FragC acc[4][NF];
    #pragma unroll
    for (int f = 0; f < 4; f++)
        #pragma unroll
        for (int j = 0; j < NF; j++) wmma::fill_fragment(acc[f][j], 0.f);
    float4 a0 = *(const float4*)(A + (size_t)(m0+ar_)*D_ + ac_);
    float4 a1 = *(const float4*)(A + (size_t)(m0+ar_)*D_ + ac_ + 4);
    if (MODE == 2) {
        float4 c0 = *(const float4*)(g_ct + (size_t)(m0+ar_)*D_ + ac_);
        float4 c1 = *(const float4*)(g_ct + (size_t)(m0+ar_)*D_ + ac_ + 4);
        a0.x=tf32r(a0.x+c0.x); a0.y=tf32r(a0.y+c0.y); a0.z=tf32r(a0.z+c0.z); a0.w=tf32r(a0.w+c0.w);
        a1.x=tf32r(a1.x+c1.x); a1.y=tf32r(a1.y+c1.y); a1.z=tf32r(a1.z+c1.z); a1.w=tf32r(a1.w+c1.w);
    }
    *(float4*)&As[0][ar_][ac_]   = a0;
    *(float4*)&As[0][ar_][ac_+4] = a1;
    __syncthreads();
    const int nit = 8;
    for (int it = 0; it < nit; it++) {
        int cur = it & 1;
        if (it + 1 < nit) {
            int k0 = (it+1)*16;
            a0 = *(const float4*)(A + (size_t)(m0+ar_)*D_ + k0 + ac_);
            a1 = *(const float4*)(A + (size_t)(m0+ar_)*D_ + k0 + ac_ + 4);
            if (MODE == 2) {
                float4 c0 = *(const float4*)(g_ct + (size_t)(m0+ar_)*D_ + k0 + ac_);
                float4 c1 = *(const float4*)(g_ct + (size_t)(m0+ar_)*D_ + k0 + ac_ + 4);
                a0.x=tf32r(a0.x+c0.x); a0.y=tf32r(a0.y+c0.y); a0.z=tf32r(a0.z+c0.z); a0.w=tf32r(a0.w+c0.w);
                a1.x=tf32r(a1.x+c1.x); a1.y=tf32r(a1.y+c1.y); a1.z=tf32r(a1.z+c1.z); a1.w=tf32r(a1.w+c1.w);
            }
        }
        #pragma unroll
        for (int ks = 0; ks < 16; ks += 8) {
            int kk = it*16 + ks;
            FragBr bf[NF];
            #pragma unroll
            for (int j = 0; j < NF; j++)
                wmma::load_matrix_sync(bf[j], Wm + (size_t)kk*NOUT + wn*(16*NF) + j*16, NOUT);
            #pragma unroll
            for (int f = 0; f < 4; f++) {
                FragAr af;
                wmma::load_matrix_sync(af, &As[cur][wm*64 + f*16][ks], 20);
                #pragma unroll
                for (int j = 0; j < NF; j++) wmma::mma_sync(acc[f][j], af, bf[j], acc[f][j]);
            }
        }
        if (it + 1 < nit) {
            int nx = cur ^ 1;
            *(float4*)&As[nx][ar_][ac_]   = a0;
            *(float4*)&As[nx][ar_][ac_+4] = a1;
            __syncthreads();
        }
    }
    if (MODE == 2) {
        int b = m0 / S_, s0 = m0 % S_;
        float* ob = outp + (size_t)b*C_*S_ + s0;
        #pragma unroll
        for (int f = 0; f < 4; f++)
            wmma::store_matrix_sync(ob + (size_t)(wn*16)*S_ + wm*64 + f*16,
                                    acc[f][0], S_, wmma::mem_col_major);
    } else {
        float* dst = (MODE == 0) ? g_h1 : g_ln;
        #pragma unroll
        for (int f = 0; f < 4; f++)
            #pragma unroll
            for (int j = 0; j < NF; j++) {
                if (MODE == 0) {
                    #pragma unroll
                    for (int e = 0; e < acc[f][j].num_elements; e++)
                        acc[f][j].x[e] = tf32r(fmaxf(acc[f][j].x[e], 0.f));
                }
                wmma::store_matrix_sync(dst + (size_t)(m0 + wm*64 + f*16)*D_ + wn*32 + j*16,
                                        acc[f][j], D_, wmma::mem_row_major);
            }
    }
}

// ---------------- launch ----------------
extern "C" void kernel_launch(void* const* d_in, const int* in_sizes, int n_in,
                              void* d_out, int out_size) {
    const float* x_lf = (const float*)d_in[0];
    const float* x_hf = (const float*)d_in[1];
    const float* W_in = (const float*)d_in[2];
    const float* W_kv = (const float*)d_in[3];
    const float* ln_g = (const float*)d_in[4];
    const float* ln_b = (const float*)d_in[5];
    const float* W_m1 = (const float*)d_in[6];
    const float* W_m2 = (const float*)d_in[7];
    const float* W_ot = (const float*)d_in[8];
    float* out = (float*)d_out;

    k_roundw<<<224, 256>>>(W_in, W_kv, W_m1, W_m2, W_ot);
    k_tokens_wmma<0><<<NPOS_/128, 256>>>(x_hf);
    k_tokens_wmma<1><<<NPOS_/128, 256>>>(x_lf);

    // sf attention
    k_fold<0><<<dim3(B_*M_SF, 2), 256>>>();
    k_score_sf<<<dim3(M_SF/64, M_SF/128, B_), 256>>>();
    k_softmax_sf<<<B_*M_SF, 256>>>();
    k_pv_sf<<<dim3((K_SF+63)/64, M_SF/128, B_), 256>>>();

    // af attention (split-K 8, wmma)
    k_fold<1><<<dim3(B_*M_AF, 2), 256>>>();
    k_score_small_wmma<1><<<dim3(3, 3, B_*8), 256>>>();
    k_softmax_small<1><<<B_*M_AF, 256>>>();
    k_pv_small_wmma<1><<<dim3(K_AF/64, 3, B_), 256>>>();

    // sa attention (split-K 16, wmma)
    k_fold<2><<<dim3(B_*M_SA, 2), 256>>>();
    k_score_small_wmma<2><<<dim3(3, 3, B_*16), 256>>>();
    k_softmax_small<2><<<B_*M_SA, 256>>>();
    k_pv_small_wmma<2><<<dim3(K_SA/64, 3, B_), 256>>>();

    // fused combine+LN, then MLP
    k_combine_ln<<<NPOS_/2, 256>>>(ln_g, ln_b);
    k_mlp_wmma<0><<<NPOS_/128, 256>>>(nullptr);
    k_mlp_wmma<1><<<NPOS_/128, 256>>>(nullptr);
    k_mlp_wmma<2><<<NPOS_/128, 256>>>(out);
}

// round 13
// speedup vs baseline: 1.3418x; 1.3418x over previous
#include <cuda_runtime.h>
#include <mma.h>
using namespace nvcuda;

// ---------------- problem constants ----------------
#define B_    4
#define C_    64
#define NA_   25
#define D_    128
#define H_    32
#define W_    32
#define S_    25600      // NA*H*W
#define NPOS_ 102400     // B*S
#define M_SF  1024
#define K_SF  800
#define M_AF  160
#define K_AF  5120
#define M_SA  160
#define K_SA  10240
#define FOFF_ (16*B_*M_AF*M_AF)

// ---------------- scratch (device globals; no allocation) ----------------
__device__ float g_q [B_*D_*S_];
__device__ float g_kv[B_*D_*S_];

__device__ float g_sfQ[B_*M_SF*K_SF];
__device__ float g_sfK[B_*M_SF*K_SF];
__device__ float g_sfO[B_*M_SF*K_SF];
__device__ float g_afQ[B_*M_AF*K_AF];
__device__ float g_afK[B_*M_AF*K_AF];
__device__ float g_afO[B_*M_AF*K_AF];
__device__ float g_saQ[B_*M_SA*K_SA];
__device__ float g_saK[B_*M_SA*K_SA];
__device__ float g_saO[B_*M_SA*K_SA];

__device__ float g_ivq_sf[B_*M_SF];
__device__ float g_ivk_sf[B_*M_SF];
__device__ float g_ivq_af[B_*M_AF];
__device__ float g_ivk_af[B_*M_AF];
__device__ float g_ivq_sa[B_*M_SA];
__device__ float g_ivk_sa[B_*M_SA];

__device__ float g_att[B_*M_SF*M_SF];

__device__ float g_ct[NPOS_*D_];
__device__ float g_ln[NPOS_*D_];
__device__ float g_h1[NPOS_*D_];

// pre-rounded weights
__device__ float g_wrk[57344];

__device__ __forceinline__ float tf32r(float x) {
    float y;
    asm("cvt.rna.tf32.f32 %0, %1;" : "=f"(y) : "f"(x));
    return y;
}

using FragAr = wmma::fragment<wmma::matrix_a, 16,16,8, wmma::precision::tf32, wmma::row_major>;
using FragAc = wmma::fragment<wmma::matrix_a, 16,16,8, wmma::precision::tf32, wmma::col_major>;
using FragBr = wmma::fragment<wmma::matrix_b, 16,16,8, wmma::precision::tf32, wmma::row_major>;
using FragBc = wmma::fragment<wmma::matrix_b, 16,16,8, wmma::precision::tf32, wmma::col_major>;
using FragC  = wmma::fragment<wmma::accumulator, 16,16,8, float>;

template<class F> __device__ __forceinline__ void cvt_tf32(F& f) {
    #pragma unroll
    for (int i = 0; i < f.num_elements; i++) f.x[i] = wmma::__float_to_tf32(f.x[i]);
}

// ---------------- 0) pre-round all weights into g_wrk ----------------
__global__ void k_roundw(const float* __restrict__ Win, const float* __restrict__ Wkv,
                         const float* __restrict__ Wm1, const float* __restrict__ Wm2,
                         const float* __restrict__ Wot) {
    int i = blockIdx.x*256 + threadIdx.x;
    if (i >= 57344) return;
    const float* src;
    int off;
    if (i < 8192)       { src = Win; off = 0; }
    else if (i < 16384) { src = Wkv; off = 8192; }
    else if (i < 32768) { src = Wm1; off = 16384; }
    else if (i < 49152) { src = Wm2; off = 32768; }
    else                { src = Wot; off = 49152; }
    g_wrk[i] = tf32r(src[i - off]);
}

// ===================================================================
// 1) token projection
// ===================================================================
template<int WHICH>
__global__ __launch_bounds__(256) void k_tokens_wmma(const float* __restrict__ x) {
    const float* Wm = g_wrk + (WHICH == 0 ? 0 : 8192);
    float* y = (WHICH == 0) ? g_q : g_kv;
    int m0 = blockIdx.x * 128;
    int b = m0 / S_, s0 = m0 % S_;
    const float* xb = x + (size_t)b*C_*S_ + s0;
    int wid = threadIdx.x >> 5, wm = wid & 1, wn = wid >> 1;
    FragC acc[4][2];
    #pragma unroll
    for (int f = 0; f < 4; f++)
        #pragma unroll
        for (int j = 0; j < 2; j++) wmma::fill_fragment(acc[f][j], 0.f);
    for (int k = 0; k < C_; k += 8) {
        FragBr bf[2];
        #pragma unroll
        for (int j = 0; j < 2; j++)
            wmma::load_matrix_sync(bf[j], Wm + (size_t)k*D_ + wn*32 + j*16, D_);
        #pragma unroll
        for (int f = 0; f < 4; f++) {
            FragAc af;
            wmma::load_matrix_sync(af, xb + (size_t)k*S_ + wm*64 + f*16, S_);
            cvt_tf32(af);
            #pragma unroll
            for (int j = 0; j < 2; j++) wmma::mma_sync(acc[f][j], af, bf[j], acc[f][j]);
        }
    }
    float* yb = y + (size_t)b*D_*S_ + s0;
    #pragma unroll
    for (int f = 0; f < 4; f++)
        #pragma unroll
        for (int j = 0; j < 2; j++)
            wmma::store_matrix_sync(yb + (size_t)(wn*32 + j*16)*S_ + wm*64 + f*16,
                                    acc[f][j], S_, wmma::mem_col_major);
}

// ---------------- 2) fold gather + inverse L2 norms (tf32-rounded output) ----------------
template<int TYPE>
__global__ void k_fold() {
    constexpr int MM  = TYPE==0 ? M_SF : (TYPE==1 ? M_AF : M_SA);
    constexpr int KK  = TYPE==0 ? K_SF : (TYPE==1 ? K_AF : K_SA);
    constexpr int OFF = TYPE==0 ? 0 : (TYPE==1 ? 32 : 64);
    int row = blockIdx.x;
    int isK = blockIdx.y;
    int b = row / MM, m = row % MM;
    const float* src = isK ? g_kv : g_q;
    float* dst; float* ivd;
    if (TYPE==0) { dst = isK ? g_sfK : g_sfQ; ivd = isK ? g_ivk_sf : g_ivq_sf; }
    else if (TYPE==1) { dst = isK ? g_afK : g_afQ; ivd = isK ? g_ivk_af : g_ivq_af; }
    else { dst = isK ? g_saK : g_saQ; ivd = isK ? g_ivk_sa : g_ivq_sa; }
    const float* base = src + ((size_t)b*D_ + OFF)*S_;
    float* drow = dst + (size_t)row*KK;
    int t = threadIdx.x;
    float ss = 0.f;
    if (TYPE == 0) {
        int ch = m >> 5, hh = m & 31;
        const float* bp = base + (size_t)ch*S_ + hh*W_;
        for (int kk = t; kk < KK; kk += 256) {
            int n = kk >> 5, ww = kk & 31;
            float v = tf32r(bp[n*(H_*W_) + ww]);
            drow[kk] = v;
            ss += v*v;
        }
    } else if (TYPE == 1) {
        int ch = m / 5, uu = m % 5;
        const float* bp = base + (size_t)ch*S_;
        for (int k = t; k < KK; k += 256) {
            int hh = k / 160, vv = (k >> 5) % 5, ww = k & 31;
            int n = uu*5 + vv;
            float v = tf32r(bp[n*(H_*W_) + hh*W_ + ww]);
            drow[k] = v;
            ss += v*v;
        }
    } else {
        int hh = m / 5, uu = m % 5;
        for (int k = t; k < KK; k += 256) {
            int ch = k / 160, vv = (k >> 5) % 5, ww = k & 31;
            int n = uu*5 + vv;
            float v = tf32r(base[(size_t)ch*S_ + n*(H_*W_) + hh*W_ + ww]);
            drow[k] = v;
            ss += v*v;
        }
    }
    __shared__ float red[256];
    red[t] = ss; __syncthreads();
    for (int st = 128; st > 0; st >>= 1) { if (t < st) red[t] += red[t + st]; __syncthreads(); }
    if (t == 0) ivd[row] = 1.f / fmaxf(sqrtf(red[0]), 1e-12f);
}

// ===================================================================
// 3a) SF raw scores (NT), wmma tf32: 128x128 tiles, 8 warps (2m x 4n)
// ===================================================================
__global__ __launch_bounds__(256) void k_score_sf() {
    int b = blockIdx.z, m0 = blockIdx.y*128, n0 = blockIdx.x*128;
    if (n0 > m0) return;                     // strictly-upper tiles never read
    const float* Ab = g_sfQ + (size_t)b*M_SF*K_SF;
    const float* Bb = g_sfK + (size_t)b*M_SF*K_SF;
    __shared__ __align__(16) float As[2][128][20];
    __shared__ __align__(16) float Bs[2][128][20];
    int t = threadIdx.x;
    int wid = t >> 5, wm = wid & 1, wn = wid >> 1;
    int lr = t >> 1, lc = (t & 1) * 8;
    FragC acc[4][2];
    #pragma unroll
    for (int f = 0; f < 4; f++)
        #pragma unroll
        for (int j = 0; j < 2; j++) wmma::fill_fragment(acc[f][j], 0.f);
    float4 a0 = *(const float4*)(Ab + (size_t)(m0+lr)*K_SF + lc);
    float4 a1 = *(const float4*)(Ab + (size_t)(m0+lr)*K_SF + lc + 4);
    float4 b0 = *(const float4*)(Bb + (size_t)(n0+lr)*K_SF + lc);
    float4 b1 = *(const float4*)(Bb + (size_t)(n0+lr)*K_SF + lc + 4);
    *(float4*)&As[0][lr][lc]   = a0;
    *(float4*)&As[0][lr][lc+4] = a1;
    *(float4*)&Bs[0][lr][lc]   = b0;
    *(float4*)&Bs[0][lr][lc+4] = b1;
    __syncthreads();
    const int nit = K_SF/16;
    for (int it = 0; it < nit; it++) {
        int cur = it & 1;
        if (it + 1 < nit) {
            int k0 = (it+1)*16;
            a0 = *(const float4*)(Ab + (size_t)(m0+lr)*K_SF + k0 + lc);
            a1 = *(const float4*)(Ab + (size_t)(m0+lr)*K_SF + k0 + lc + 4);
            b0 = *(const float4*)(Bb + (size_t)(n0+lr)*K_SF + k0 + lc);
            b1 = *(const float4*)(Bb + (size_t)(n0+lr)*K_SF + k0 + lc + 4);
        }
        #pragma unroll
        for (int ks = 0; ks < 16; ks += 8) {
            FragBc bf[2];
            #pragma unroll
            for (int j = 0; j < 2; j++)
                wmma::load_matrix_sync(bf[j], &Bs[cur][wn*32 + j*16][ks], 20);
            #pragma unroll
            for (int f = 0; f < 4; f++) {
                FragAr af;
                wmma::load_matrix_sync(af, &As[cur][wm*64 + f*16][ks], 20);
                #pragma unroll
                for (int j = 0; j < 2; j++) wmma::mma_sync(acc[f][j], af, bf[j], acc[f][j]);
            }
        }
        if (it + 1 < nit) {
            int nx = cur ^ 1;
            *(float4*)&As[nx][lr][lc]   = a0;
            *(float4*)&As[nx][lr][lc+4] = a1;
            *(float4*)&Bs[nx][lr][lc]   = b0;
            *(float4*)&Bs[nx][lr][lc+4] = b1;
            __syncthreads();
        }
    }
    float* att = g_att + (size_t)b*M_SF*M_SF;
    #pragma unroll
    for (int f = 0; f < 4; f++)
        #pragma unroll
        for (int j = 0; j < 2; j++)
            wmma::store_matrix_sync(att + (size_t)(m0 + wm*64 + f*16)*M_SF + n0 + wn*32 + j*16,
                                    acc[f][j], M_SF, wmma::mem_row_major);
}

// ===================================================================
// 4a) SF softmax (scale + mask + softmax); writes tf32-rounded probs
// ===================================================================
__global__ __launch_bounds__(256) void k_softmax_sf() {
    int blk = blockIdx.x;
    int b = blk >> 10, m = blk & 1023;
    float* p = g_att + ((size_t)b*M_SF + m)*M_SF;
    int LIMW = ((m >> 7) + 1) << 7;
    float qn = g_ivq_sf[b*M_SF + m];
    const float* ivk = g_ivk_sf + b*M_SF;
    int t = threadIdx.x;
    __shared__ float red[256];
    float vv[4];
    float mx = -3.4e38f;
    #pragma unroll
    for (int i = 0; i < 4; i++) {
        int k = t + i*256;
        if (k < LIMW) {
            float v = (k <= m) ? p[k]*qn*ivk[k] : -3.4e38f;
            vv[i] = v; mx = fmaxf(mx, v);
        }
    }
    red[t] = mx; __syncthreads();
    for (int st = 128; st > 0; st >>= 1) { if (t < st) red[t] = fmaxf(red[t], red[t+st]); __syncthreads(); }
    mx = red[0]; __syncthreads();
    float s = 0.f;
    #pragma unroll
    for (int i = 0; i < 4; i++) {
        int k = t + i*256;
        if (k < LIMW) {
            float e = (k <= m) ? expf(vv[i] - mx) : 0.f;
            vv[i] = e; s += e;
        }
    }
    red[t] = s; __syncthreads();
    for (int st = 128; st > 0; st >>= 1) { if (t < st) red[t] += red[t+st]; __syncthreads(); }
    float inv = 1.f / red[0];
    #pragma unroll
    for (int i = 0; i < 4; i++) {
        int k = t + i*256;
        if (k < LIMW) p[k] = tf32r(vv[i]*inv);
    }
}

// ===================================================================
// 5a) SF O = P @ V (NN), wmma tf32, causal bound
// ===================================================================
__global__ __launch_bounds__(256) void k_pv_sf() {
    int b = blockIdx.z, m0 = blockIdx.y*128, k0 = blockIdx.x*64;
    const float* Pb = g_att + (size_t)b*M_SF*M_SF;
    const float* Vb = g_sfK + (size_t)b*M_SF*K_SF;
    __shared__ __align__(16) float As[2][128][20];
    __shared__ __align__(16) float Bs[2][16][68];
    int t = threadIdx.x;
    int wid = t >> 5, wm = wid & 1, wn = wid >> 1;
    int ar_ = t >> 1, ac_ = (t & 1) * 8;
    int vr_ = t >> 4, vc_ = (t & 15) * 4;
    bool bok = (k0 + vc_) < K_SF;
    FragC acc[4];
    #pragma unroll
    for (int i = 0; i < 4; i++) wmma::fill_fragment(acc[i], 0.f);
    float4 a0 = *(const float4*)(Pb + (size_t)(m0+ar_)*M_SF + ac_);
    float4 a1 = *(const float4*)(Pb + (size_t)(m0+ar_)*M_SF + ac_ + 4);
    float4 b0 = bok ? *(const float4*)(Vb + (size_t)vr_*K_SF + k0 + vc_) : make_float4(0,0,0,0);
    *(float4*)&As[0][ar_][ac_]   = a0;
    *(float4*)&As[0][ar_][ac_+4] = a1;
    *(float4*)&Bs[0][vr_][vc_]   = b0;
    __syncthreads();
    const int nit = (m0 + 128) / 16;
    for (int it = 0; it < nit; it++) {
        int cur = it & 1;
        if (it + 1 < nit) {
            int n0 = (it+1)*16;
            a0 = *(const float4*)(Pb + (size_t)(m0+ar_)*M_SF + n0 + ac_);
            a1 = *(const float4*)(Pb + (size_t)(m0+ar_)*M_SF + n0 + ac_ + 4);
            b0 = bok ? *(const float4*)(Vb + (size_t)(n0+vr_)*K_SF + k0 + vc_) : make_float4(0,0,0,0);
        }
        #pragma unroll
        for (int ks = 0; ks < 16; ks += 8) {
            FragBr bf;
            wmma::load_matrix_sync(bf, &Bs[cur][ks][wn*16], 68);
            #pragma unroll
            for (int f = 0; f < 4; f++) {
                FragAr af;
                wmma::load_matrix_sync(af, &As[cur][wm*64 + f*16][ks], 20);
                wmma::mma_sync(acc[f], af, bf, acc[f]);
            }
        }
        if (it + 1 < nit) {
            int nx = cur ^ 1;
            *(float4*)&As[nx][ar_][ac_]   = a0;
            *(float4*)&As[nx][ar_][ac_+4] = a1;
            *(float4*)&Bs[nx][vr_][vc_]   = b0;
            __syncthreads();
        }
    }
    float* O = g_sfO + (size_t)b*M_SF*K_SF;
    int col0 = k0 + wn*16;
    if (col0 < K_SF) {
        #pragma unroll
        for (int f = 0; f < 4; f++)
            wmma::store_matrix_sync(O + (size_t)(m0 + wm*64 + f*16)*K_SF + col0,
                                    acc[f], K_SF, wmma::mem_row_major);
    }
}

// ===================================================================
// 3b) af/sa raw scores, split-K (SIMT)
// ===================================================================
template<int TYPE>
__global__ __launch_bounds__(256) void k_score_small() {
    constexpr int MM = 160;
    constexpr int KK = TYPE==1 ? K_AF : K_SA;
    constexpr int CH = TYPE==1 ? 8 : 16;
    constexpr int CHK = KK / CH;
    const float* Qf = TYPE==1 ? g_afQ : g_saQ;
    const float* Kf = TYPE==1 ? g_afK : g_saK;
    int z = blockIdx.z;
    int b = z / CH, ch = z % CH;
    int m0 = blockIdx.y*64, n0 = blockIdx.x*64;
    if (n0 > m0 + 63) return;
    const float* Ab = Qf + (size_t)b*MM*KK;
    const float* Bb = Kf + (size_t)b*MM*KK;
    __shared__ __align__(16) float As[16][64];
    __shared__ __align__(16) float Bs[16][64];
    int t = threadIdx.x, tn = t & 15, tm = t >> 4;
    int lr = t >> 2, lc = (t & 3) << 2;
    float acc[4][4] = {};
    int kbeg = ch*CHK, kend = kbeg + CHK;
    for (int k0 = kbeg; k0 < kend; k0 += 16) {
        float4 av = make_float4(0,0,0,0), bv = make_float4(0,0,0,0);
        if (m0 + lr < MM) av = *(const float4*)(Ab + (size_t)(m0+lr)*KK + k0 + lc);
        if (n0 + lr < MM) bv = *(const float4*)(Bb + (size_t)(n0+lr)*KK + k0 + lc);
        __syncthreads();
        As[lc+0][lr]=av.x; As[lc+1][lr]=av.y; As[lc+2][lr]=av.z; As[lc+3][lr]=av.w;
        Bs[lc+0][lr]=bv.x; Bs[lc+1][lr]=bv.y; Bs[lc+2][lr]=bv.z; Bs[lc+3][lr]=bv.w;
        __syncthreads();
        #pragma unroll
        for (int kk = 0; kk < 16; kk++) {
            float4 a = *(const float4*)&As[kk][tm << 2];
            float4 bq = *(const float4*)&Bs[kk][tn << 2];
            acc[0][0]+=a.x*bq.x; acc[0][1]+=a.x*bq.y; acc[0][2]+=a.x*bq.z; acc[0][3]+=a.x*bq.w;
            acc[1][0]+=a.y*bq.x; acc[1][1]+=a.y*bq.y; acc[1][2]+=a.y*bq.z; acc[1][3]+=a.y*bq.w;
            acc[2][0]+=a.z*bq.x; acc[2][1]+=a.z*bq.y; acc[2][2]+=a.z*bq.z; acc[2][3]+=a.z*bq.w;
            acc[3][0]+=a.w*bq.x; acc[3][1]+=a.w*bq.y; acc[3][2]+=a.w*bq.z; acc[3][3]+=a.w*bq.w;
        }
    }
    float* part = g_att + ((size_t)(ch*B_ + b)*MM)*MM;
    #pragma unroll
    for (int i = 0; i < 4; i++) {
        int m = m0 + (tm<<2) + i; if (m >= MM) continue;
        #pragma unroll
        for (int j = 0; j < 4; j++) {
            int n = n0 + (tn<<2) + j; if (n >= MM) continue;
            part[(size_t)m*MM + n] = acc[i][j];
        }
    }
}

// ---------------- 4b) af/sa softmax over split-K partials ----------------
template<int TYPE>
__global__ __launch_bounds__(256) void k_softmax_small() {
    constexpr int MM = 160;
    constexpr int CH = TYPE==1 ? 8 : 16;
    const float* ivq = TYPE==1 ? g_ivq_af : g_ivq_sa;
    const float* ivk = TYPE==1 ? g_ivk_af : g_ivk_sa;
    int blk = blockIdx.x;
    int b = blk / MM, m = blk % MM;
    int t = threadIdx.x;
    float v = -3.4e38f;
    if (t < MM && t <= m) {
        float s = 0.f;
        #pragma unroll 4
        for (int ch = 0; ch < CH; ch++)
            s += g_att[(((size_t)(ch*B_ + b))*MM + m)*MM + t];
        v = s * ivq[b*MM + m] * ivk[b*MM + t];
    }
    __shared__ float red[256];
    red[t] = v; __syncthreads();
    for (int st = 128; st > 0; st >>= 1) { if (t < st) red[t] = fmaxf(red[t], red[t+st]); __syncthreads(); }
    float mx = red[0]; __syncthreads();
    float e = (t < MM && t <= m) ? expf(v - mx) : 0.f;
    red[t] = e; __syncthreads();
    for (int st = 128; st > 0; st >>= 1) { if (t < st) red[t] += red[t+st]; __syncthreads(); }
    float inv = 1.f / red[0];
    if (t < MM) g_att[FOFF_ + ((size_t)b*MM + m)*MM + t] = e*inv;
}

// ---------------- 5b) af/sa O = P @ V (SIMT) ----------------
template<int TYPE>
__global__ __launch_bounds__(256) void k_pv() {
    constexpr int MM = 160;
    constexpr int KK = TYPE==1 ? K_AF : K_SA;
    const float* V = TYPE==1 ? g_afK : g_saK;
    float* O = TYPE==1 ? g_afO : g_saO;
    int b = blockIdx.z, m0 = blockIdx.y*64, k0 = blockIdx.x*64;
    int t = threadIdx.x, tn = t & 15, tm = t >> 4;
    const float* Pb = g_att + FOFF_ + (size_t)b*MM*MM;
    const float* Vb = V + (size_t)b*MM*KK;
    __shared__ __align__(16) float As[16][64];
    __shared__ __align__(16) float Bs[16][64];
    int lr = t >> 2, lc = (t & 3) << 2;
    int br = t >> 4, bc = (t & 15) << 2;
    float acc[4][4] = {};
    int NLIM = (m0 + 64 < MM) ? m0 + 64 : MM;
    for (int n0 = 0; n0 < NLIM; n0 += 16) {
        float4 av = make_float4(0,0,0,0), bv = make_float4(0,0,0,0);
        if (m0 + lr < MM) av = *(const float4*)(Pb + (size_t)(m0+lr)*MM + n0 + lc);
        if (n0 + br < MM) bv = *(const float4*)(Vb + (size_t)(n0+br)*KK + k0 + bc);
        __syncthreads();
        As[lc+0][lr]=av.x; As[lc+1][lr]=av.y; As[lc+2][lr]=av.z; As[lc+3][lr]=av.w;
        *(float4*)&Bs[br][bc] = bv;
        __syncthreads();
        #pragma unroll
        for (int nn = 0; nn < 16; nn++) {
            float4 a = *(const float4*)&As[nn][tm << 2];
            float4 bq = *(const float4*)&Bs[nn][tn << 2];
            acc[0][0]+=a.x*bq.x; acc[0][1]+=a.x*bq.y; acc[0][2]+=a.x*bq.z; acc[0][3]+=a.x*bq.w;
            acc[1][0]+=a.y*bq.x; acc[1][1]+=a.y*bq.y; acc[1][2]+=a.y*bq.z; acc[1][3]+=a.y*bq.w;
            acc[2][0]+=a.z*bq.x; acc[2][1]+=a.z*bq.y; acc[2][2]+=a.z*bq.z; acc[2][3]+=a.z*bq.w;
            acc[3][0]+=a.w*bq.x; acc[3][1]+=a.w*bq.y; acc[3][2]+=a.w*bq.z; acc[3][3]+=a.w*bq.w;
        }
    }
    #pragma unroll
    for (int i = 0; i < 4; i++) {
        int m = m0 + (tm<<2) + i; if (m >= MM) continue;
        #pragma unroll
        for (int j = 0; j < 4; j++) {
            int k = k0 + (tn<<2) + j;
            O[((size_t)b*MM + m)*KK + k] = acc[i][j];
        }
    }
}

// ===================================================================
// 6+7) fused unfold+residual+LayerNorm (ln output tf32-rounded)
// ===================================================================
__global__ __launch_bounds__(256) void k_combine_ln(const float* __restrict__ gamma,
                                                    const float* __restrict__ beta) {
    int t = threadIdx.x;
    int tok = t >> 7;
    int dc = t & 127;
    int T = blockIdx.x*2 + tok;
    int ww = T & 31, hh = (T >> 5) & 31;
    int bn = T >> 10;
    int b = bn / 25, n = bn % 25;
    int uu = n / 5, vv = n % 5;
    float r = g_kv[((size_t)b*D_ + dc)*S_ + n*(H_*W_) + hh*W_ + ww];
    float o;
    if (dc < 32) {
        int m = dc*32 + hh, k = n*32 + ww;
        o = g_sfO[((size_t)b*M_SF + m)*K_SF + k];
    } else if (dc < 64) {
        int m = (dc-32)*5 + uu, k = (hh*5 + vv)*32 + ww;
        o = g_afO[((size_t)b*M_AF + m)*K_AF + k];
    } else {
        int m = hh*5 + uu, k = ((dc-64)*5 + vv)*32 + ww;
        o = g_saO[((size_t)b*M_SA + m)*K_SA + k];
    }
    float v = o + r;
    g_ct[(size_t)T*D_ + dc] = v;
    float s = v;
    #pragma unroll
    for (int of = 16; of > 0; of >>= 1) s += __shfl_xor_sync(0xffffffffu, s, of);
    __shared__ float wsum[2][4];
    int wg = (t >> 5) & 3;
    if ((t & 31) == 0) wsum[tok][wg] = s;
    __syncthreads();
    float mu = (wsum[tok][0]+wsum[tok][1]+wsum[tok][2]+wsum[tok][3]) * (1.f/128.f);
    float cx = v - mu;
    float sq = cx*cx;
    #pragma unroll
    for (int of = 16; of > 0; of >>= 1) sq += __shfl_xor_sync(0xffffffffu, sq, of);
    __shared__ float wsq[2][4];
    if ((t & 31) == 0) wsq[tok][wg] = sq;
    __syncthreads();
    float var = (wsq[tok][0]+wsq[tok][1]+wsq[tok][2]+wsq[tok][3]) * (1.f/128.f);
    float inv = rsqrtf(var + 1e-5f);
    g_ln[(size_t)T*D_ + dc] = tf32r(cx*inv*gamma[dc] + beta[dc]);
}

// ===================================================================
// 8) MLP gemms, wmma tf32
// ===================================================================
template<int MODE>
__global__ __launch_bounds__(256) void k_mlp_wmma(float* __restrict__ outp) {
    constexpr int NOUT = (MODE == 2) ? 64 : 128;
    constexpr int NF   = (MODE == 2) ? 1 : 2;
    const float* Wm = g_wrk + (MODE == 0 ? 16384 : (MODE == 1 ? 32768 : 49152));
    const float* A = (MODE == 1) ? g_h1 : g_ln;
    int m0 = blockIdx.x * 128;
    __shared__ __align__(16) float As[2][128][20];
    int t = threadIdx.x;
    int wid = t >> 5, wm = wid & 1, wn = wid >> 1;
    int ar_ = t >> 1, ac_ = (t & 1) * 8;
    FragC acc[4][NF];
    #pragma unroll
    for (int f = 0; f < 4; f++)
        #pragma unroll
        for (int j = 0; j < NF; j++) wmma::fill_fragment(acc[f][j], 0.f);
    float4 a0 = *(const float4*)(A + (size_t)(m0+ar_)*D_ + ac_);
    float4 a1 = *(const float4*)(A + (size_t)(m0+ar_)*D_ + ac_ + 4);
    if (MODE == 2) {
        float4 c0 = *(const float4*)(g_ct + (size_t)(m0+ar_)*D_ + ac_);
        float4 c1 = *(const float4*)(g_ct + (size_t)(m0+ar_)*D_ + ac_ + 4);
        a0.x=tf32r(a0.x+c0.x); a0.y=tf32r(a0.y+c0.y); a0.z=tf32r(a0.z+c0.z); a0.w=tf32r(a0.w+c0.w);
        a1.x=tf32r(a1.x+c1.x); a1.y=tf32r(a1.y+c1.y); a1.z=tf32r(a1.z+c1.z); a1.w=tf32r(a1.w+c1.w);
    }
    *(float4*)&As[0][ar_][ac_]   = a0;
    *(float4*)&As[0][ar_][ac_+4] = a1;
    __syncthreads();
    const int nit = 8;
    for (int it = 0; it < nit; it++) {
        int cur = it & 1;
        if (it + 1 < nit) {
            int k0 = (it+1)*16;
            a0 = *(const float4*)(A + (size_t)(m0+ar_)*D_ + k0 + ac_);
            a1 = *(const float4*)(A + (size_t)(m0+ar_)*D_ + k0 + ac_ + 4);
            if (MODE == 2) {
                float4 c0 = *(const float4*)(g_ct + (size_t)(m0+ar_)*D_ + k0 + ac_);
                float4 c1 = *(const float4*)(g_ct + (size_t)(m0+ar_)*D_ + k0 + ac_ + 4);
                a0.x=tf32r(a0.x+c0.x); a0.y=tf32r(a0.y+c0.y); a0.z=tf32r(a0.z+c0.z); a0.w=tf32r(a0.w+c0.w);
                a1.x=tf32r(a1.x+c1.x); a1.y=tf32r(a1.y+c1.y); a1.z=tf32r(a1.z+c1.z); a1.w=tf32r(a1.w+c1.w);
            }
        }
        #pragma unroll
        for (int ks = 0; ks < 16; ks += 8) {
            int kk = it*16 + ks;
            FragBr bf[NF];
            #pragma unroll
            for (int j = 0; j < NF; j++)
                wmma::load_matrix_sync(bf[j], Wm + (size_t)kk*NOUT + wn*(16*NF) + j*16, NOUT);
            #pragma unroll
            for (int f = 0; f < 4; f++) {
                FragAr af;
                wmma::load_matrix_sync(af, &As[cur][wm*64 + f*16][ks], 20);
                #pragma unroll
                for (int j = 0; j < NF; j++) wmma::mma_sync(acc[f][j], af, bf[j], acc[f][j]);
            }
        }
        if (it + 1 < nit) {
            int nx = cur ^ 1;
            *(float4*)&As[nx][ar_][ac_]   = a0;
            *(float4*)&As[nx][ar_][ac_+4] = a1;
            __syncthreads();
        }
    }
    if (MODE == 2) {
        int b = m0 / S_, s0 = m0 % S_;
        float* ob = outp + (size_t)b*C_*S_ + s0;
        #pragma unroll
        for (int f = 0; f < 4; f++)
            wmma::store_matrix_sync(ob + (size_t)(wn*16)*S_ + wm*64 + f*16,
                                    acc[f][0], S_, wmma::mem_col_major);
    } else {
        float* dst = (MODE == 0) ? g_h1 : g_ln;
        #pragma unroll
        for (int f = 0; f < 4; f++)
            #pragma unroll
            for (int j = 0; j < NF; j++) {
                if (MODE == 0) {
                    #pragma unroll
                    for (int e = 0; e < acc[f][j].num_elements; e++)
                        acc[f][j].x[e] = tf32r(fmaxf(acc[f][j].x[e], 0.f));
                }
                wmma::store_matrix_sync(dst + (size_t)(m0 + wm*64 + f*16)*D_ + wn*32 + j*16,
                                        acc[f][j], D_, wmma::mem_row_major);
            }
    }
}

// ---------------- launch ----------------
extern "C" void kernel_launch(void* const* d_in, const int* in_sizes, int n_in,
                              void* d_out, int out_size) {
    const float* x_lf = (const float*)d_in[0];
    const float* x_hf = (const float*)d_in[1];
    const float* W_in = (const float*)d_in[2];
    const float* W_kv = (const float*)d_in[3];
    const float* ln_g = (const float*)d_in[4];
    const float* ln_b = (const float*)d_in[5];
    const float* W_m1 = (const float*)d_in[6];
    const float* W_m2 = (const float*)d_in[7];
    const float* W_ot = (const float*)d_in[8];
    float* out = (float*)d_out;

    k_roundw<<<224, 256>>>(W_in, W_kv, W_m1, W_m2, W_ot);
    k_tokens_wmma<0><<<NPOS_/128, 256>>>(x_hf);
    k_tokens_wmma<1><<<NPOS_/128, 256>>>(x_lf);

    // sf attention
    k_fold<0><<<dim3(B_*M_SF, 2), 256>>>();
    k_score_sf<<<dim3(M_SF/128, M_SF/128, B_), 256>>>();
    k_softmax_sf<<<B_*M_SF, 256>>>();
    k_pv_sf<<<dim3((K_SF+63)/64, M_SF/128, B_), 256>>>();

    // af attention (split-K 8)
    k_fold<1><<<dim3(B_*M_AF, 2), 256>>>();
    k_score_small<1><<<dim3(3, 3, B_*8), 256>>>();
    k_softmax_small<1><<<B_*M_AF, 256>>>();
    k_pv<1><<<dim3(K_AF/64, 3, B_), 256>>>();

    // sa attention (split-K 16)
    k_fold<2><<<dim3(B_*M_SA, 2), 256>>>();
    k_score_small<2><<<dim3(3, 3, B_*16), 256>>>();
    k_softmax_small<2><<<B_*M_SA, 256>>>();
    k_pv<2><<<dim3(K_SA/64, 3, B_), 256>>>();

    // fused combine+LN, then MLP
    k_combine_ln<<<NPOS_/2, 256>>>(ln_g, ln_b);
    k_mlp_wmma<0><<<NPOS_/128, 256>>>(nullptr);
    k_mlp_wmma<1><<<NPOS_/128, 256>>>(nullptr);
    k_mlp_wmma<2><<<NPOS_/128, 256>>>(out);
}

// round 17
// speedup vs baseline: 1.3949x; 1.0396x over previous
#include <cuda_runtime.h>
#include <mma.h>
using namespace nvcuda;

// ---------------- problem constants ----------------
#define B_    4
#define C_    64
#define NA_   25
#define D_    128
#define H_    32
#define W_    32
#define S_    25600      // NA*H*W
#define NPOS_ 102400     // B*S
#define M_SF  1024
#define K_SF  800
#define M_AF  160
#define K_AF  5120
#define M_SA  160
#define K_SA  10240
#define FOFF_ (16*B_*M_AF*M_AF)

// ---------------- scratch (device globals; no allocation) ----------------
__device__ float g_q [B_*D_*S_];
__device__ float g_kv[B_*D_*S_];

__device__ float g_sfQ[B_*M_SF*K_SF];
__device__ float g_sfK[B_*M_SF*K_SF];
__device__ float g_sfO[B_*M_SF*K_SF];
__device__ float g_afQ[B_*M_AF*K_AF];
__device__ float g_afK[B_*M_AF*K_AF];
__device__ float g_afO[B_*M_AF*K_AF];
__device__ float g_saQ[B_*M_SA*K_SA];
__device__ float g_saK[B_*M_SA*K_SA];
__device__ float g_saO[B_*M_SA*K_SA];

__device__ float g_ivq_sf[B_*M_SF];
__device__ float g_ivk_sf[B_*M_SF];
__device__ float g_ivq_af[B_*M_AF];
__device__ float g_ivk_af[B_*M_AF];
__device__ float g_ivq_sa[B_*M_SA];
__device__ float g_ivk_sa[B_*M_SA];

__device__ float g_att[B_*M_SF*M_SF];

__device__ float g_ct[NPOS_*D_];
__device__ float g_ln[NPOS_*D_];

// pre-rounded weights: [0]=W_in [8192]=W_kv [16384]=W_m1 [32768]=W_m2 [49152]=W_out
__device__ float g_wrk[57344];

__device__ __forceinline__ float tf32r(float x) {
    float y;
    asm("cvt.rna.tf32.f32 %0, %1;" : "=f"(y) : "f"(x));
    return y;
}

using FragAr = wmma::fragment<wmma::matrix_a, 16,16,8, wmma::precision::tf32, wmma::row_major>;
using FragAc = wmma::fragment<wmma::matrix_a, 16,16,8, wmma::precision::tf32, wmma::col_major>;
using FragBr = wmma::fragment<wmma::matrix_b, 16,16,8, wmma::precision::tf32, wmma::row_major>;
using FragBc = wmma::fragment<wmma::matrix_b, 16,16,8, wmma::precision::tf32, wmma::col_major>;
using FragC  = wmma::fragment<wmma::accumulator, 16,16,8, float>;

template<class F> __device__ __forceinline__ void cvt_tf32(F& f) {
    #pragma unroll
    for (int i = 0; i < f.num_elements; i++) f.x[i] = wmma::__float_to_tf32(f.x[i]);
}

// ---------------- 0) pre-round all weights into g_wrk ----------------
__global__ void k_roundw(const float* __restrict__ Win, const float* __restrict__ Wkv,
                         const float* __restrict__ Wm1, const float* __restrict__ Wm2,
                         const float* __restrict__ Wot) {
    int i = blockIdx.x*256 + threadIdx.x;
    if (i >= 57344) return;
    const float* src;
    int off;
    if (i < 8192)       { src = Win; off = 0; }
    else if (i < 16384) { src = Wkv; off = 8192; }
    else if (i < 32768) { src = Wm1; off = 16384; }
    else if (i < 49152) { src = Wm2; off = 32768; }
    else                { src = Wot; off = 49152; }
    g_wrk[i] = tf32r(src[i - off]);
}

// ===================================================================
// 1) token projection
// ===================================================================
template<int WHICH>
__global__ __launch_bounds__(256) void k_tokens_wmma(const float* __restrict__ x) {
    const float* Wm = g_wrk + (WHICH == 0 ? 0 : 8192);
    float* y = (WHICH == 0) ? g_q : g_kv;
    int m0 = blockIdx.x * 128;
    int b = m0 / S_, s0 = m0 % S_;
    const float* xb = x + (size_t)b*C_*S_ + s0;
    int wid = threadIdx.x >> 5, wm = wid & 1, wn = wid >> 1;
    FragC acc[4][2];
    #pragma unroll
    for (int f = 0; f < 4; f++)
        #pragma unroll
        for (int j = 0; j < 2; j++) wmma::fill_fragment(acc[f][j], 0.f);
    for (int k = 0; k < C_; k += 8) {
        FragBr bf[2];
        #pragma unroll
        for (int j = 0; j < 2; j++)
            wmma::load_matrix_sync(bf[j], Wm + (size_t)k*D_ + wn*32 + j*16, D_);
        #pragma unroll
        for (int f = 0; f < 4; f++) {
            FragAc af;
            wmma::load_matrix_sync(af, xb + (size_t)k*S_ + wm*64 + f*16, S_);
            cvt_tf32(af);
            #pragma unroll
            for (int j = 0; j < 2; j++) wmma::mma_sync(acc[f][j], af, bf[j], acc[f][j]);
        }
    }
    float* yb = y + (size_t)b*D_*S_ + s0;
    #pragma unroll
    for (int f = 0; f < 4; f++)
        #pragma unroll
        for (int j = 0; j < 2; j++)
            wmma::store_matrix_sync(yb + (size_t)(wn*32 + j*16)*S_ + wm*64 + f*16,
                                    acc[f][j], S_, wmma::mem_col_major);
}

// ---------------- 2) fold gather + inverse L2 norms (tf32-rounded output) ----------------
template<int TYPE>
__global__ void k_fold() {
    constexpr int MM  = TYPE==0 ? M_SF : (TYPE==1 ? M_AF : M_SA);
    constexpr int KK  = TYPE==0 ? K_SF : (TYPE==1 ? K_AF : K_SA);
    constexpr int OFF = TYPE==0 ? 0 : (TYPE==1 ? 32 : 64);
    int row = blockIdx.x;
    int isK = blockIdx.y;
    int b = row / MM, m = row % MM;
    const float* src = isK ? g_kv : g_q;
    float* dst; float* ivd;
    if (TYPE==0) { dst = isK ? g_sfK : g_sfQ; ivd = isK ? g_ivk_sf : g_ivq_sf; }
    else if (TYPE==1) { dst = isK ? g_afK : g_afQ; ivd = isK ? g_ivk_af : g_ivq_af; }
    else { dst = isK ? g_saK : g_saQ; ivd = isK ? g_ivk_sa : g_ivq_sa; }
    const float* base = src + ((size_t)b*D_ + OFF)*S_;
    float* drow = dst + (size_t)row*KK;
    int t = threadIdx.x;
    float ss = 0.f;
    if (TYPE == 0) {
        int ch = m >> 5, hh = m & 31;
        const float* bp = base + (size_t)ch*S_ + hh*W_;
        for (int kk = t; kk < KK; kk += 256) {
            int n = kk >> 5, ww = kk & 31;
            float v = tf32r(bp[n*(H_*W_) + ww]);
            drow[kk] = v;
            ss += v*v;
        }
    } else if (TYPE == 1) {
        int ch = m / 5, uu = m % 5;
        const float* bp = base + (size_t)ch*S_;
        for (int k = t; k < KK; k += 256) {
            int hh = k / 160, vv = (k >> 5) % 5, ww = k & 31;
            int n = uu*5 + vv;
            float v = tf32r(bp[n*(H_*W_) + hh*W_ + ww]);
            drow[k] = v;
            ss += v*v;
        }
    } else {
        int hh = m / 5, uu = m % 5;
        for (int k = t; k < KK; k += 256) {
            int ch = k / 160, vv = (k >> 5) % 5, ww = k & 31;
            int n = uu*5 + vv;
            float v = tf32r(base[(size_t)ch*S_ + n*(H_*W_) + hh*W_ + ww]);
            drow[k] = v;
            ss += v*v;
        }
    }
    __shared__ float red[256];
    red[t] = ss; __syncthreads();
    for (int st = 128; st > 0; st >>= 1) { if (t < st) red[t] += red[t + st]; __syncthreads(); }
    if (t == 0) ivd[row] = 1.f / fmaxf(sqrtf(red[0]), 1e-12f);
}

// ===================================================================
// 3a) SF raw scores (NT), wmma tf32: 128x64 tiles (proven R9 config)
// ===================================================================
__global__ __launch_bounds__(256) void k_score_sf() {
    int b = blockIdx.z, m0 = blockIdx.y*128, n0 = blockIdx.x*64;
    if (n0 > m0 + 127) return;
    const float* Ab = g_sfQ + (size_t)b*M_SF*K_SF;
    const float* Bb = g_sfK + (size_t)b*M_SF*K_SF;
    __shared__ __align__(16) float As[2][128][20];
    __shared__ __align__(16) float Bs[2][64][20];
    int t = threadIdx.x;
    int wid = t >> 5, wm = wid & 1, wn = wid >> 1;
    int ar_ = t >> 1, ac_ = (t & 1) * 8;
    int br_ = t >> 2, bc_ = (t & 3) * 4;
    FragC acc[4];
    #pragma unroll
    for (int i = 0; i < 4; i++) wmma::fill_fragment(acc[i], 0.f);
    float4 a0 = *(const float4*)(Ab + (size_t)(m0+ar_)*K_SF + ac_);
    float4 a1 = *(const float4*)(Ab + (size_t)(m0+ar_)*K_SF + ac_ + 4);
    float4 b0 = *(const float4*)(Bb + (size_t)(n0+br_)*K_SF + bc_);
    *(float4*)&As[0][ar_][ac_]   = a0;
    *(float4*)&As[0][ar_][ac_+4] = a1;
    *(float4*)&Bs[0][br_][bc_]   = b0;
    __syncthreads();
    const int nit = K_SF/16;
    for (int it = 0; it < nit; it++) {
        int cur = it & 1;
        if (it + 1 < nit) {
            int k0 = (it+1)*16;
            a0 = *(const float4*)(Ab + (size_t)(m0+ar_)*K_SF + k0 + ac_);
            a1 = *(const float4*)(Ab + (size_t)(m0+ar_)*K_SF + k0 + ac_ + 4);
            b0 = *(const float4*)(Bb + (size_t)(n0+br_)*K_SF + k0 + bc_);
        }
        #pragma unroll
        for (int ks = 0; ks < 16; ks += 8) {
            FragBc bf;
            wmma::load_matrix_sync(bf, &Bs[cur][wn*16][ks], 20);
            #pragma unroll
            for (int f = 0; f < 4; f++) {
                FragAr af;
                wmma::load_matrix_sync(af, &As[cur][wm*64 + f*16][ks], 20);
                wmma::mma_sync(acc[f], af, bf, acc[f]);
            }
        }
        if (it + 1 < nit) {
            int nx = cur ^ 1;
            *(float4*)&As[nx][ar_][ac_]   = a0;
            *(float4*)&As[nx][ar_][ac_+4] = a1;
            *(float4*)&Bs[nx][br_][bc_]   = b0;
            __syncthreads();
        }
    }
    float* att = g_att + (size_t)b*M_SF*M_SF;
    #pragma unroll
    for (int f = 0; f < 4; f++)
        wmma::store_matrix_sync(att + (size_t)(m0 + wm*64 + f*16)*M_SF + n0 + wn*16,
                                acc[f], M_SF, wmma::mem_row_major);
}

// ===================================================================
// 4a) SF softmax (scale + mask + softmax); writes tf32-rounded probs
// ===================================================================
__global__ __launch_bounds__(256) void k_softmax_sf() {
    int blk = blockIdx.x;
    int b = blk >> 10, m = blk & 1023;
    float* p = g_att + ((size_t)b*M_SF + m)*M_SF;
    int LIMW = ((m >> 7) + 1) << 7;
    float qn = g_ivq_sf[b*M_SF + m];
    const float* ivk = g_ivk_sf + b*M_SF;
    int t = threadIdx.x;
    __shared__ float red[256];
    float vv[4];
    float mx = -3.4e38f;
    #pragma unroll
    for (int i = 0; i < 4; i++) {
        int k = t + i*256;
        if (k < LIMW) {
            float v = (k <= m) ? p[k]*qn*ivk[k] : -3.4e38f;
            vv[i] = v; mx = fmaxf(mx, v);
        }
    }
    red[t] = mx; __syncthreads();
    for (int st = 128; st > 0; st >>= 1) { if (t < st) red[t] = fmaxf(red[t], red[t+st]); __syncthreads(); }
    mx = red[0]; __syncthreads();
    float s = 0.f;
    #pragma unroll
    for (int i = 0; i < 4; i++) {
        int k = t + i*256;
        if (k < LIMW) {
            float e = (k <= m) ? expf(vv[i] - mx) : 0.f;
            vv[i] = e; s += e;
        }
    }
    red[t] = s; __syncthreads();
    for (int st = 128; st > 0; st >>= 1) { if (t < st) red[t] += red[t+st]; __syncthreads(); }
    float inv = 1.f / red[0];
    #pragma unroll
    for (int i = 0; i < 4; i++) {
        int k = t + i*256;
        if (k < LIMW) p[k] = tf32r(vv[i]*inv);
    }
}

// ===================================================================
// 5a) SF O = P @ V (NN), wmma tf32, causal bound
// ===================================================================
__global__ __launch_bounds__(256) void k_pv_sf() {
    int b = blockIdx.z, m0 = blockIdx.y*128, k0 = blockIdx.x*64;
    const float* Pb = g_att + (size_t)b*M_SF*M_SF;
    const float* Vb = g_sfK + (size_t)b*M_SF*K_SF;
    __shared__ __align__(16) float As[2][128][20];
    __shared__ __align__(16) float Bs[2][16][68];
    int t = threadIdx.x;
    int wid = t >> 5, wm = wid & 1, wn = wid >> 1;
    int ar_ = t >> 1, ac_ = (t & 1) * 8;
    int vr_ = t >> 4, vc_ = (t & 15) * 4;
    bool bok = (k0 + vc_) < K_SF;
    FragC acc[4];
    #pragma unroll
    for (int i = 0; i < 4; i++) wmma::fill_fragment(acc[i], 0.f);
    float4 a0 = *(const float4*)(Pb + (size_t)(m0+ar_)*M_SF + ac_);
    float4 a1 = *(const float4*)(Pb + (size_t)(m0+ar_)*M_SF + ac_ + 4);
    float4 b0 = bok ? *(const float4*)(Vb + (size_t)vr_*K_SF + k0 + vc_) : make_float4(0,0,0,0);
    *(float4*)&As[0][ar_][ac_]   = a0;
    *(float4*)&As[0][ar_][ac_+4] = a1;
    *(float4*)&Bs[0][vr_][vc_]   = b0;
    __syncthreads();
    const int nit = (m0 + 128) / 16;
    for (int it = 0; it < nit; it++) {
        int cur = it & 1;
        if (it + 1 < nit) {
            int n0 = (it+1)*16;
            a0 = *(const float4*)(Pb + (size_t)(m0+ar_)*M_SF + n0 + ac_);
            a1 = *(const float4*)(Pb + (size_t)(m0+ar_)*M_SF + n0 + ac_ + 4);
            b0 = bok ? *(const float4*)(Vb + (size_t)(n0+vr_)*K_SF + k0 + vc_) : make_float4(0,0,0,0);
        }
        #pragma unroll
        for (int ks = 0; ks < 16; ks += 8) {
            FragBr bf;
            wmma::load_matrix_sync(bf, &Bs[cur][ks][wn*16], 68);
            #pragma unroll
            for (int f = 0; f < 4; f++) {
                FragAr af;
                wmma::load_matrix_sync(af, &As[cur][wm*64 + f*16][ks], 20);
                wmma::mma_sync(acc[f], af, bf, acc[f]);
            }
        }
        if (it + 1 < nit) {
            int nx = cur ^ 1;
            *(float4*)&As[nx][ar_][ac_]   = a0;
            *(float4*)&As[nx][ar_][ac_+4] = a1;
            *(float4*)&Bs[nx][vr_][vc_]   = b0;
            __syncthreads();
        }
    }
    float* O = g_sfO + (size_t)b*M_SF*K_SF;
    int col0 = k0 + wn*16;
    if (col0 < K_SF) {
        #pragma unroll
        for (int f = 0; f < 4; f++)
            wmma::store_matrix_sync(O + (size_t)(m0 + wm*64 + f*16)*K_SF + col0,
                                    acc[f], K_SF, wmma::mem_row_major);
    }
}

// ===================================================================
// 3b) af/sa raw scores, split-K (SIMT)
// ===================================================================
template<int TYPE>
__global__ __launch_bounds__(256) void k_score_small() {
    constexpr int MM = 160;
    constexpr int KK = TYPE==1 ? K_AF : K_SA;
    constexpr int CH = TYPE==1 ? 8 : 16;
    constexpr int CHK = KK / CH;
    const float* Qf = TYPE==1 ? g_afQ : g_saQ;
    const float* Kf = TYPE==1 ? g_afK : g_saK;
    int z = blockIdx.z;
    int b = z / CH, ch = z % CH;
    int m0 = blockIdx.y*64, n0 = blockIdx.x*64;
    if (n0 > m0 + 63) return;
    const float* Ab = Qf + (size_t)b*MM*KK;
    const float* Bb = Kf + (size_t)b*MM*KK;
    __shared__ __align__(16) float As[16][64];
    __shared__ __align__(16) float Bs[16][64];
    int t = threadIdx.x, tn = t & 15, tm = t >> 4;
    int lr = t >> 2, lc = (t & 3) << 2;
    float acc[4][4] = {};
    int kbeg = ch*CHK, kend = kbeg + CHK;
    for (int k0 = kbeg; k0 < kend; k0 += 16) {
        float4 av = make_float4(0,0,0,0), bv = make_float4(0,0,0,0);
        if (m0 + lr < MM) av = *(const float4*)(Ab + (size_t)(m0+lr)*KK + k0 + lc);
        if (n0 + lr < MM) bv = *(const float4*)(Bb + (size_t)(n0+lr)*KK + k0 + lc);
        __syncthreads();
        As[lc+0][lr]=av.x; As[lc+1][lr]=av.y; As[lc+2][lr]=av.z; As[lc+3][lr]=av.w;
        Bs[lc+0][lr]=bv.x; Bs[lc+1][lr]=bv.y; Bs[lc+2][lr]=bv.z; Bs[lc+3][lr]=bv.w;
        __syncthreads();
        #pragma unroll
        for (int kk = 0; kk < 16; kk++) {
            float4 a = *(const float4*)&As[kk][tm << 2];
            float4 bq = *(const float4*)&Bs[kk][tn << 2];
            acc[0][0]+=a.x*bq.x; acc[0][1]+=a.x*bq.y; acc[0][2]+=a.x*bq.z; acc[0][3]+=a.x*bq.w;
            acc[1][0]+=a.y*bq.x; acc[1][1]+=a.y*bq.y; acc[1][2]+=a.y*bq.z; acc[1][3]+=a.y*bq.w;
            acc[2][0]+=a.z*bq.x; acc[2][1]+=a.z*bq.y; acc[2][2]+=a.z*bq.z; acc[2][3]+=a.z*bq.w;
            acc[3][0]+=a.w*bq.x; acc[3][1]+=a.w*bq.y; acc[3][2]+=a.w*bq.z; acc[3][3]+=a.w*bq.w;
        }
    }
    float* part = g_att + ((size_t)(ch*B_ + b)*MM)*MM;
    #pragma unroll
    for (int i = 0; i < 4; i++) {
        int m = m0 + (tm<<2) + i; if (m >= MM) continue;
        #pragma unroll
        for (int j = 0; j < 4; j++) {
            int n = n0 + (tn<<2) + j; if (n >= MM) continue;
            part[(size_t)m*MM + n] = acc[i][j];
        }
    }
}

// ---------------- 4b) af/sa softmax over split-K partials ----------------
template<int TYPE>
__global__ __launch_bounds__(256) void k_softmax_small() {
    constexpr int MM = 160;
    constexpr int CH = TYPE==1 ? 8 : 16;
    const float* ivq = TYPE==1 ? g_ivq_af : g_ivq_sa;
    const float* ivk = TYPE==1 ? g_ivk_af : g_ivk_sa;
    int blk = blockIdx.x;
    int b = blk / MM, m = blk % MM;
    int t = threadIdx.x;
    float v = -3.4e38f;
    if (t < MM && t <= m) {
        float s = 0.f;
        #pragma unroll 4
        for (int ch = 0; ch < CH; ch++)
            s += g_att[(((size_t)(ch*B_ + b))*MM + m)*MM + t];
        v = s * ivq[b*MM + m] * ivk[b*MM + t];
    }
    __shared__ float red[256];
    red[t] = v; __syncthreads();
    for (int st = 128; st > 0; st >>= 1) { if (t < st) red[t] = fmaxf(red[t], red[t+st]); __syncthreads(); }
    float mx = red[0]; __syncthreads();
    float e = (t < MM && t <= m) ? expf(v - mx) : 0.f;
    red[t] = e; __syncthreads();
    for (int st = 128; st > 0; st >>= 1) { if (t < st) red[t] += red[t+st]; __syncthreads(); }
    float inv = 1.f / red[0];
    if (t < MM) g_att[FOFF_ + ((size_t)b*MM + m)*MM + t] = e*inv;
}

// ---------------- 5b) af/sa O = P @ V (SIMT) ----------------
template<int TYPE>
__global__ __launch_bounds__(256) void k_pv() {
    constexpr int MM = 160;
    constexpr int KK = TYPE==1 ? K_AF : K_SA;
    const float* V = TYPE==1 ? g_afK : g_saK;
    float* O = TYPE==1 ? g_afO : g_saO;
    int b = blockIdx.z, m0 = blockIdx.y*64, k0 = blockIdx.x*64;
    int t = threadIdx.x, tn = t & 15, tm = t >> 4;
    const float* Pb = g_att + FOFF_ + (size_t)b*MM*MM;
    const float* Vb = V + (size_t)b*MM*KK;
    __shared__ __align__(16) float As[16][64];
    __shared__ __align__(16) float Bs[16][64];
    int lr = t >> 2, lc = (t & 3) << 2;
    int br = t >> 4, bc = (t & 15) << 2;
    float acc[4][4] = {};
    int NLIM = (m0 + 64 < MM) ? m0 + 64 : MM;
    for (int n0 = 0; n0 < NLIM; n0 += 16) {
        float4 av = make_float4(0,0,0,0), bv = make_float4(0,0,0,0);
        if (m0 + lr < MM) av = *(const float4*)(Pb + (size_t)(m0+lr)*MM + n0 + lc);
        if (n0 + br < MM) bv = *(const float4*)(Vb + (size_t)(n0+br)*KK + k0 + bc);
        __syncthreads();
        As[lc+0][lr]=av.x; As[lc+1][lr]=av.y; As[lc+2][lr]=av.z; As[lc+3][lr]=av.w;
        *(float4*)&Bs[br][bc] = bv;
        __syncthreads();
        #pragma unroll
        for (int nn = 0; nn < 16; nn++) {
            float4 a = *(const float4*)&As[nn][tm << 2];
            float4 bq = *(const float4*)&Bs[nn][tn << 2];
            acc[0][0]+=a.x*bq.x; acc[0][1]+=a.x*bq.y; acc[0][2]+=a.x*bq.z; acc[0][3]+=a.x*bq.w;
            acc[1][0]+=a.y*bq.x; acc[1][1]+=a.y*bq.y; acc[1][2]+=a.y*bq.z; acc[1][3]+=a.y*bq.w;
            acc[2][0]+=a.z*bq.x; acc[2][1]+=a.z*bq.y; acc[2][2]+=a.z*bq.z; acc[2][3]+=a.z*bq.w;
            acc[3][0]+=a.w*bq.x; acc[3][1]+=a.w*bq.y; acc[3][2]+=a.w*bq.z; acc[3][3]+=a.w*bq.w;
        }
    }
    #pragma unroll
    for (int i = 0; i < 4; i++) {
        int m = m0 + (tm<<2) + i; if (m >= MM) continue;
        #pragma unroll
        for (int j = 0; j < 4; j++) {
            int k = k0 + (tn<<2) + j;
            O[((size_t)b*MM + m)*KK + k] = acc[i][j];
        }
    }
}

// ===================================================================
// 6+7) fused unfold+residual+LayerNorm (ln output tf32-rounded)
// ===================================================================
__global__ __launch_bounds__(256) void k_combine_ln(const float* __restrict__ gamma,
                                                    const float* __restrict__ beta) {
    int t = threadIdx.x;
    int tok = t >> 7;
    int dc = t & 127;
    int T = blockIdx.x*2 + tok;
    int ww = T & 31, hh = (T >> 5) & 31;
    int bn = T >> 10;
    int b = bn / 25, n = bn % 25;
    int uu = n / 5, vv = n % 5;
    float r = g_kv[((size_t)b*D_ + dc)*S_ + n*(H_*W_) + hh*W_ + ww];
    float o;
    if (dc < 32) {
        int m = dc*32 + hh, k = n*32 + ww;
        o = g_sfO[((size_t)b*M_SF + m)*K_SF + k];
    } else if (dc < 64) {
        int m = (dc-32)*5 + uu, k = (hh*5 + vv)*32 + ww;
        o = g_afO[((size_t)b*M_AF + m)*K_AF + k];
    } else {
        int m = hh*5 + uu, k = ((dc-64)*5 + vv)*32 + ww;
        o = g_saO[((size_t)b*M_SA + m)*K_SA + k];
    }
    float v = o + r;
    g_ct[(size_t)T*D_ + dc] = v;
    float s = v;
    #pragma unroll
    for (int of = 16; of > 0; of >>= 1) s += __shfl_xor_sync(0xffffffffu, s, of);
    __shared__ float wsum[2][4];
    int wg = (t >> 5) & 3;
    if ((t & 31) == 0) wsum[tok][wg] = s;
    __syncthreads();
    float mu = (wsum[tok][0]+wsum[tok][1]+wsum[tok][2]+wsum[tok][3]) * (1.f/128.f);
    float cx = v - mu;
    float sq = cx*cx;
    #pragma unroll
    for (int of = 16; of > 0; of >>= 1) sq += __shfl_xor_sync(0xffffffffu, sq, of);
    __shared__ float wsq[2][4];
    if ((t & 31) == 0) wsq[tok][wg] = sq;
    __syncthreads();
    float var = (wsq[tok][0]+wsq[tok][1]+wsq[tok][2]+wsq[tok][3]) * (1.f/128.f);
    float inv = rsqrtf(var + 1e-5f);
    g_ln[(size_t)T*D_ + dc] = tf32r(cx*inv*gamma[dc] + beta[dc]);
}

// ===================================================================
// 8) FUSED MLP: out = (relu(ln@W1)@W2 + ct) @ Wout, one kernel.
//    64-row tiles; single 64x132 smem buffer reused for h1 then h2.
//    GEMM1 A-fragments come straight from global g_ln (L1-cached, 4x reuse).
// ===================================================================
__global__ __launch_bounds__(256) void k_mlp_fused(float* __restrict__ outp) {
    const float* W1 = g_wrk + 16384;
    const float* W2 = g_wrk + 32768;
    const float* Wo = g_wrk + 49152;
    int m0 = blockIdx.x * 64;
    __shared__ __align__(16) float Hs[64][132];
    int t = threadIdx.x;
    int wid = t >> 5, wm = wid & 1, wn = wid >> 1;   // 2m x 4n warps

    // ---- GEMM1: h1 = round(relu(ln @ W1)) -> Hs
    FragC acc1[2][2];
    #pragma unroll
    for (int f = 0; f < 2; f++)
        #pragma unroll
        for (int j = 0; j < 2; j++) wmma::fill_fragment(acc1[f][j], 0.f);
    for (int k0 = 0; k0 < 128; k0 += 8) {
        FragBr bf[2];
        #pragma unroll
        for (int j = 0; j < 2; j++)
            wmma::load_matrix_sync(bf[j], W1 + (size_t)k0*D_ + wn*32 + j*16, D_);
        #pragma unroll
        for (int f = 0; f < 2; f++) {
            FragAr af;
            wmma::load_matrix_sync(af, g_ln + (size_t)(m0 + wm*32 + f*16)*D_ + k0, D_);
            #pragma unroll
            for (int j = 0; j < 2; j++) wmma::mma_sync(acc1[f][j], af, bf[j], acc1[f][j]);
        }
    }
    #pragma unroll
    for (int f = 0; f < 2; f++)
        #pragma unroll
        for (int j = 0; j < 2; j++) {
            #pragma unroll
            for (int e = 0; e < acc1[f][j].num_elements; e++)
                acc1[f][j].x[e] = tf32r(fmaxf(acc1[f][j].x[e], 0.f));
            wmma::store_matrix_sync(&Hs[wm*32 + f*16][wn*32 + j*16], acc1[f][j], 132,
                                    wmma::mem_row_major);
        }
    __syncthreads();

    // ---- GEMM2: h2 = h1 @ W2 (regs)
    FragC acc2[2][2];
    #pragma unroll
    for (int f = 0; f < 2; f++)
        #pragma unroll
        for (int j = 0; j < 2; j++) wmma::fill_fragment(acc2[f][j], 0.f);
    for (int k0 = 0; k0 < 128; k0 += 8) {
        FragBr bf[2];
        #pragma unroll
        for (int j = 0; j < 2; j++)
            wmma::load_matrix_sync(bf[j], W2 + (size_t)k0*D_ + wn*32 + j*16, D_);
        #pragma unroll
        for (int f = 0; f < 2; f++) {
            FragAr af;
            wmma::load_matrix_sync(af, &Hs[wm*32 + f*16][k0], 132);
            #pragma unroll
            for (int j = 0; j < 2; j++) wmma::mma_sync(acc2[f][j], af, bf[j], acc2[f][j]);
        }
    }
    __syncthreads();        // all Hs reads done
    #pragma unroll
    for (int f = 0; f < 2; f++)
        #pragma unroll
        for (int j = 0; j < 2; j++)
            wmma::store_matrix_sync(&Hs[wm*32 + f*16][wn*32 + j*16], acc2[f][j], 132,
                                    wmma::mem_row_major);
    __syncthreads();

    // ---- elementwise: Hs = round(h2 + ct)
    #pragma unroll
    for (int i = 0; i < 32; i++) {
        int idx = t + i*256;
        int r = idx >> 7, c = idx & 127;
        Hs[r][c] = tf32r(Hs[r][c] + g_ct[(size_t)(m0 + r)*D_ + c]);
    }
    __syncthreads();

    // ---- GEMM3: out = Hs @ Wout (N=64), scatter store
    FragC acc3[2];
    #pragma unroll
    for (int f = 0; f < 2; f++) wmma::fill_fragment(acc3[f], 0.f);
    for (int k0 = 0; k0 < 128; k0 += 8) {
        FragBr bf;
        wmma::load_matrix_sync(bf, Wo + (size_t)k0*64 + wn*16, 64);
        #pragma unroll
        for (int f = 0; f < 2; f++) {
            FragAr af;
            wmma::load_matrix_sync(af, &Hs[wm*32 + f*16][k0], 132);
            wmma::mma_sync(acc3[f], af, bf, acc3[f]);
        }
    }
    int b = m0 / S_, s0 = m0 % S_;
    float* ob = outp + (size_t)b*C_*S_ + s0;
    #pragma unroll
    for (int f = 0; f < 2; f++)
        wmma::store_matrix_sync(ob + (size_t)(wn*16)*S_ + wm*32 + f*16,
                                acc3[f], S_, wmma::mem_col_major);
}

// ---------------- launch ----------------
extern "C" void kernel_launch(void* const* d_in, const int* in_sizes, int n_in,
                              void* d_out, int out_size) {
    const float* x_lf = (const float*)d_in[0];
    const float* x_hf = (const float*)d_in[1];
    const float* W_in = (const float*)d_in[2];
    const float* W_kv = (const float*)d_in[3];
    const float* ln_g = (const float*)d_in[4];
    const float* ln_b = (const float*)d_in[5];
    const float* W_m1 = (const float*)d_in[6];
    const float* W_m2 = (const float*)d_in[7];
    const float* W_ot = (const float*)d_in[8];
    float* out = (float*)d_out;

    k_roundw<<<224, 256>>>(W_in, W_kv, W_m1, W_m2, W_ot);
    k_tokens_wmma<0><<<NPOS_/128, 256>>>(x_hf);
    k_tokens_wmma<1><<<NPOS_/128, 256>>>(x_lf);

    // sf attention
    k_fold<0><<<dim3(B_*M_SF, 2), 256>>>();
    k_score_sf<<<dim3(M_SF/64, M_SF/128, B_), 256>>>();
    k_softmax_sf<<<B_*M_SF, 256>>>();
    k_pv_sf<<<dim3((K_SF+63)/64, M_SF/128, B_), 256>>>();

    // af attention (split-K 8)
    k_fold<1><<<dim3(B_*M_AF, 2), 256>>>();
    k_score_small<1><<<dim3(3, 3, B_*8), 256>>>();
    k_softmax_small<1><<<B_*M_AF, 256>>>();
    k_pv<1><<<dim3(K_AF/64, 3, B_), 256>>>();

    // sa attention (split-K 16)
    k_fold<2><<<dim3(B_*M_SA, 2), 256>>>();
    k_score_small<2><<<dim3(3, 3, B_*16), 256>>>();
    k_softmax_small<2><<<B_*M_SA, 256>>>();
    k_pv<2><<<dim3(K_SA/64, 3, B_), 256>>>();

    // fused combine+LN, then fully-fused MLP
    k_combine_ln<<<NPOS_/2, 256>>>(ln_g, ln_b);
    k_mlp_fused<<<NPOS_/64, 256>>>(out);
}